// round 2
// baseline (speedup 1.0000x reference)
#include <cuda_runtime.h>
#include <cub/cub.cuh>
#include <math.h>

#define HFE 100
#define WFE 152
#define HW  15200
#define CIN 512
#define CMID 512
#define KTOT 4608           // 9 taps * 512 channels
#define NBOX 136800
#define NPRE 6000
#define NPOST 300
#define OUT_LOC 0
#define OUT_SC  547200
#define OUT_ROI 820800
#define IMG_H 1600.0f
#define IMG_W 2432.0f
#define NEG_INF (__int_as_float(0xff800000))

// ---------------- device scratch (no allocs allowed) ----------------
__device__ float g_wt[KTOT * CMID];        // transposed weights [k][m]
__device__ float g_h[CMID * HW];           // conv1 output (channel-major)
__device__ float g_roi[NBOX * 4];
__device__ float g_sc[NBOX];
__device__ unsigned g_idx[NBOX];
__device__ float g_sc_s[NBOX];
__device__ unsigned g_idx_s[NBOX];
__device__ unsigned char g_tmp[32 << 20];  // cub temp

__constant__ int c_dy[9] = {-1,-1,-1, 0,0,0, 1,1,1};
__constant__ int c_dx[9] = {-1, 0, 1,-1,0,1,-1,0,1};

// ---------------- weight transpose: OIHW -> [k = t*512+c][m] ----------------
__global__ void k_transpose(const float* __restrict__ w)
{
    int i = blockIdx.x * 256 + threadIdx.x;
    if (i >= KTOT * CMID) return;
    int m = i / KTOT;
    int r = i - m * KTOT;
    int c = r / 9;
    int t = r - c * 9;
    g_wt[(t * 512 + c) * 512 + m] = w[i];
}

// ---------------- implicit-GEMM conv 3x3 + bias + ReLU ----------------
// C[m][n] = sum_k A[k][m] * B[k][n],  m = out channel, n = pixel
__global__ __launch_bounds__(256, 2) void k_conv(const float* __restrict__ xin,
                                                 const float* __restrict__ bias)
{
    __shared__ float As[16][128];
    __shared__ float Bs[16][128];

    const int tid = threadIdx.x;
    const int bn = blockIdx.x * 128;   // pixel base
    const int bm = blockIdx.y * 128;   // out-channel base
    const int tx = tid & 15;
    const int ty = tid >> 4;
    const int nn = tid & 127;
    const int kk0 = tid >> 7;          // 0 or 1
    const int ra = tid >> 5;           // 0..7
    const int ca = (tid & 31) * 4;

    const int p = bn + nn;
    const bool pvalid = p < HW;
    const int py = p / WFE;
    const int px = p - py * WFE;

    float4 a0, a1;
    float bfrag[8];
    float acc[8][8];
#pragma unroll
    for (int i = 0; i < 8; i++)
#pragma unroll
        for (int j = 0; j < 8; j++) acc[i][j] = 0.f;

    // prologue loads for k0 = 0
    a0 = *reinterpret_cast<const float4*>(&g_wt[(0 + ra) * 512 + bm + ca]);
    a1 = *reinterpret_cast<const float4*>(&g_wt[(8 + ra) * 512 + bm + ca]);
#pragma unroll
    for (int i = 0; i < 8; i++) {
        int k = kk0 + 2 * i;
        int t = k >> 9;
        int c = k & 511;
        int iy = py + c_dy[t];
        int ix = px + c_dx[t];
        float v = 0.f;
        if (pvalid && iy >= 0 && iy < HFE && ix >= 0 && ix < WFE)
            v = xin[c * HW + iy * WFE + ix];
        bfrag[i] = v;
    }

    for (int k0 = 0; k0 < KTOT; k0 += 16) {
        // commit staged regs to smem
        *reinterpret_cast<float4*>(&As[ra][ca]) = a0;
        *reinterpret_cast<float4*>(&As[ra + 8][ca]) = a1;
#pragma unroll
        for (int i = 0; i < 8; i++) Bs[kk0 + 2 * i][nn] = bfrag[i];
        __syncthreads();

        // prefetch next chunk
        if (k0 + 16 < KTOT) {
            int kn = k0 + 16;
            a0 = *reinterpret_cast<const float4*>(&g_wt[(kn + ra) * 512 + bm + ca]);
            a1 = *reinterpret_cast<const float4*>(&g_wt[(kn + ra + 8) * 512 + bm + ca]);
#pragma unroll
            for (int i = 0; i < 8; i++) {
                int k = kn + kk0 + 2 * i;
                int t = k >> 9;
                int c = k & 511;
                int iy = py + c_dy[t];
                int ix = px + c_dx[t];
                float v = 0.f;
                if (pvalid && iy >= 0 && iy < HFE && ix >= 0 && ix < WFE)
                    v = xin[c * HW + iy * WFE + ix];
                bfrag[i] = v;
            }
        }

        // compute
#pragma unroll
        for (int kk = 0; kk < 16; kk++) {
            float4 av0 = *reinterpret_cast<const float4*>(&As[kk][ty * 8]);
            float4 av1 = *reinterpret_cast<const float4*>(&As[kk][ty * 8 + 4]);
            float4 bv0 = *reinterpret_cast<const float4*>(&Bs[kk][tx * 8]);
            float4 bv1 = *reinterpret_cast<const float4*>(&Bs[kk][tx * 8 + 4]);
            float am[8] = {av0.x, av0.y, av0.z, av0.w, av1.x, av1.y, av1.z, av1.w};
            float bb[8] = {bv0.x, bv0.y, bv0.z, bv0.w, bv1.x, bv1.y, bv1.z, bv1.w};
#pragma unroll
            for (int i = 0; i < 8; i++)
#pragma unroll
                for (int j = 0; j < 8; j++)
                    acc[i][j] = fmaf(am[i], bb[j], acc[i][j]);
        }
        __syncthreads();
    }

    // epilogue: bias + relu, store to g_h
    const int nb = bn + tx * 8;
#pragma unroll
    for (int i = 0; i < 8; i++) {
        int m = bm + ty * 8 + i;
        float bv = bias[m];
        float4 v0 = make_float4(fmaxf(acc[i][0] + bv, 0.f), fmaxf(acc[i][1] + bv, 0.f),
                                fmaxf(acc[i][2] + bv, 0.f), fmaxf(acc[i][3] + bv, 0.f));
        float4 v1 = make_float4(fmaxf(acc[i][4] + bv, 0.f), fmaxf(acc[i][5] + bv, 0.f),
                                fmaxf(acc[i][6] + bv, 0.f), fmaxf(acc[i][7] + bv, 0.f));
        if (nb + 3 < HW) *reinterpret_cast<float4*>(&g_h[m * HW + nb]) = v0;
        if (nb + 7 < HW) *reinterpret_cast<float4*>(&g_h[m * HW + nb + 4]) = v1;
    }
}

// ---------------- fused 1x1 convs (score 18ch + loc 36ch) ----------------
// writes rpn_loc and rpn_score directly into d_out in NHWC order
__global__ __launch_bounds__(128) void k_1x1(const float* __restrict__ sw,
                                             const float* __restrict__ sb,
                                             const float* __restrict__ lw,
                                             const float* __restrict__ lb,
                                             float* __restrict__ out)
{
    __shared__ float ws[128][54];
    int p = blockIdx.x * 128 + threadIdx.x;
    bool ok = p < HW;
    float acc[54];
#pragma unroll
    for (int j = 0; j < 54; j++) acc[j] = 0.f;

    for (int cc = 0; cc < 512; cc += 128) {
        __syncthreads();
        // load weight chunk [128 channels][54 outputs]; channels 0..17 score, 18..53 loc
        for (int it = 0; it < 54; it++) {
            int cl = threadIdx.x;
            ws[cl][it] = (it < 18) ? sw[it * 512 + cc + cl]
                                   : lw[(it - 18) * 512 + cc + cl];
        }
        __syncthreads();
        if (ok) {
#pragma unroll 4
            for (int cl = 0; cl < 128; cl++) {
                float hv = g_h[(cc + cl) * HW + p];
#pragma unroll
                for (int j = 0; j < 54; j++) acc[j] = fmaf(ws[cl][j], hv, acc[j]);
            }
        }
    }
    if (ok) {
#pragma unroll
        for (int j = 0; j < 18; j++) out[OUT_SC + p * 18 + j] = acc[j] + sb[j];
#pragma unroll
        for (int j = 0; j < 36; j++) out[OUT_LOC + p * 36 + j] = acc[18 + j] + lb[j];
    }
}

// ---------------- decode: softmax fg, anchors, loc2bbox, clip, validity ----------------
__global__ void k_decode(const float* __restrict__ out)
{
    int i = blockIdx.x * 256 + threadIdx.x;
    if (i >= NBOX) return;
    int p = i / 9;
    int a = i - p * 9;
    int yy = p / WFE;
    int xx = p - yy * WFE;

    // anchor base in double, matching numpy, then cast to f32
    const double RS[3] = {0.5, 1.0, 2.0};
    const double SS[3] = {8.0, 16.0, 32.0};
    int ir = a / 3, js = a - ir * 3;
    double hh = 16.0 * SS[js] * sqrt(RS[ir]);
    double wa = 16.0 * SS[js] * sqrt(1.0 / RS[ir]);
    float sy = (float)(yy * 16);
    float sx = (float)(xx * 16);
    float A0 = sy + (float)(8.0 - hh * 0.5);
    float A1 = sx + (float)(8.0 - wa * 0.5);
    float A2 = sy + (float)(8.0 + hh * 0.5);
    float A3 = sx + (float)(8.0 + wa * 0.5);

    float h = A2 - A0, w = A3 - A1;
    float cy = A0 + 0.5f * h, cx = A1 + 0.5f * w;
    float dy = out[OUT_LOC + p * 36 + a * 4 + 0];
    float dx = out[OUT_LOC + p * 36 + a * 4 + 1];
    float dh = out[OUT_LOC + p * 36 + a * 4 + 2];
    float dw = out[OUT_LOC + p * 36 + a * 4 + 3];
    float cy2 = dy * h + cy;
    float cx2 = dx * w + cx;
    float h2 = expf(dh) * h;
    float w2 = expf(dw) * w;
    float r0 = fminf(fmaxf(cy2 - 0.5f * h2, 0.f), IMG_H);
    float r1 = fminf(fmaxf(cx2 - 0.5f * w2, 0.f), IMG_W);
    float r2 = fminf(fmaxf(cy2 + 0.5f * h2, 0.f), IMG_H);
    float r3 = fminf(fmaxf(cx2 + 0.5f * w2, 0.f), IMG_W);
    bool valid = (r2 - r0 >= 16.f) && (r3 - r1 >= 16.f);

    float s0 = out[OUT_SC + p * 18 + a * 2];
    float s1 = out[OUT_SC + p * 18 + a * 2 + 1];
    float mm = fmaxf(s0, s1);
    float e0 = expf(s0 - mm), e1 = expf(s1 - mm);
    float fg = e1 / (e0 + e1);

    g_roi[i * 4 + 0] = r0;
    g_roi[i * 4 + 1] = r1;
    g_roi[i * 4 + 2] = r2;
    g_roi[i * 4 + 3] = r3;
    g_sc[i] = valid ? fg : NEG_INF;
    g_idx[i] = (unsigned)i;
}

// ---------------- greedy NMS (exact reference semantics) + rois write ----------------
__global__ void k_nms(float* __restrict__ out)
{
    extern __shared__ float sm[];
    float* ssc = sm;
    float* sy1 = sm + NPRE;
    float* sx1 = sm + 2 * NPRE;
    float* sy2 = sm + 3 * NPRE;
    float* sx2 = sm + 4 * NPRE;
    float* sar = sm + 5 * NPRE;
    __shared__ int ksel[NPOST];

    int tid = threadIdx.x;
    for (int i = tid; i < NPRE; i += 256) {
        unsigned idx = g_idx_s[i];
        float4 b = reinterpret_cast<const float4*>(g_roi)[idx];
        ssc[i] = g_sc_s[i];
        sy1[i] = b.x; sx1[i] = b.y; sy2[i] = b.z; sx2[i] = b.w;
        sar[i] = (b.z - b.x) * (b.w - b.y);
    }
    __syncthreads();

    int kc = 0;
    for (int i = 0; i < NPRE; i++) {
        float sc = ssc[i];
        if (sc == NEG_INF) break;   // sorted: everything after is invalid too
        float y1 = sy1[i], x1 = sx1[i], y2 = sy2[i], x2 = sx2[i], ar = sar[i];
        int sup = 0;
        for (int j = tid; j < kc; j += 256) {
            int t = ksel[j];
            float ih = fmaxf(fminf(sy2[t], y2) - fmaxf(sy1[t], y1), 0.f);
            float iw = fmaxf(fminf(sx2[t], x2) - fmaxf(sx1[t], x1), 0.f);
            float inter = ih * iw;
            float iou = inter / (sar[t] + ar - inter + 1e-9f);
            if (iou > 0.7f) sup = 1;
        }
        sup = __syncthreads_or(sup);
        if (!sup) {
            if (tid == 0) ksel[kc] = i;
            kc++;
            __syncthreads();
            if (kc == NPOST) break;
        }
    }

    for (int r = tid; r < NPOST; r += 256) {
        float v0 = 0.f, v1 = 0.f, v2 = 0.f, v3 = 0.f;
        if (r < kc) {
            int t = ksel[r];
            v0 = sy1[t]; v1 = sx1[t]; v2 = sy2[t]; v3 = sx2[t];
        }
        out[OUT_ROI + r * 4 + 0] = v0;
        out[OUT_ROI + r * 4 + 1] = v1;
        out[OUT_ROI + r * 4 + 2] = v2;
        out[OUT_ROI + r * 4 + 3] = v3;
    }
}

// ---------------- host launcher ----------------
extern "C" void kernel_launch(void* const* d_in, const int* in_sizes, int n_in,
                              void* d_out, int out_size)
{
    const float* x  = (const float*)d_in[0];
    const float* w1 = (const float*)d_in[1];
    const float* b1 = (const float*)d_in[2];
    const float* sw = (const float*)d_in[3];
    const float* sb = (const float*)d_in[4];
    const float* lw = (const float*)d_in[5];
    const float* lb = (const float*)d_in[6];
    float* out = (float*)d_out;

    k_transpose<<<(KTOT * CMID + 255) / 256, 256>>>(w1);
    k_conv<<<dim3((HW + 127) / 128, CMID / 128), 256>>>(x, b1);
    k_1x1<<<(HW + 127) / 128, 128>>>(sw, sb, lw, lb, out);
    k_decode<<<(NBOX + 255) / 256, 256>>>(out);

    void *p_sc, *p_idx, *p_scs, *p_idxs, *p_tmp;
    cudaGetSymbolAddress(&p_sc, g_sc);
    cudaGetSymbolAddress(&p_idx, g_idx);
    cudaGetSymbolAddress(&p_scs, g_sc_s);
    cudaGetSymbolAddress(&p_idxs, g_idx_s);
    cudaGetSymbolAddress(&p_tmp, g_tmp);

    size_t tb = 0;
    cub::DeviceRadixSort::SortPairsDescending(nullptr, tb,
        (const float*)p_sc, (float*)p_scs,
        (const unsigned*)p_idx, (unsigned*)p_idxs, NBOX);
    if (tb > (size_t)(32u << 20)) tb = (size_t)(32u << 20);
    cub::DeviceRadixSort::SortPairsDescending(p_tmp, tb,
        (const float*)p_sc, (float*)p_scs,
        (const unsigned*)p_idx, (unsigned*)p_idxs, NBOX);

    int nms_smem = 6 * NPRE * (int)sizeof(float);
    cudaFuncSetAttribute(k_nms, cudaFuncAttributeMaxDynamicSharedMemorySize, nms_smem);
    k_nms<<<1, 256, nms_smem>>>(out);
}